// round 7
// baseline (speedup 1.0000x reference)
#include <cuda_runtime.h>
#include <cstdint>
#include <cstddef>

// Problem constants (fixed by the dataset generator)
#define VOCAB 50000
#define D     300
#define BATCH 64
#define LC    32
#define TT    256
#define LT    64
#define NSEL  5

// Scratch (no allocations allowed -> device globals)
__device__ float g_scores[BATCH * TT];
__device__ int   g_topidx[BATCH * NSEL];

// ---------------------------------------------------------------------------
// Helpers: f32x2 packed FMA (sm_103a FFMA2, PTX-only) and cp.async
// ---------------------------------------------------------------------------
__device__ __forceinline__ unsigned long long pack2(float x, float y) {
    unsigned long long r;
    asm("mov.b64 %0, {%1, %2};" : "=l"(r) : "f"(x), "f"(y));
    return r;
}
__device__ __forceinline__ void unpack2(unsigned long long v, float& x, float& y) {
    asm("mov.b64 {%0, %1}, %2;" : "=f"(x), "=f"(y) : "l"(v));
}
__device__ __forceinline__ void ffma2(unsigned long long& d,
                                      unsigned long long a,
                                      unsigned long long b) {
    asm("fma.rn.f32x2 %0, %1, %2, %0;" : "+l"(d) : "l"(a), "l"(b));
}
__device__ __forceinline__ unsigned smem_u32(const void* p) {
    return (unsigned)__cvta_generic_to_shared(p);
}
__device__ __forceinline__ void cp16(unsigned dst, const float* src, int szbytes) {
    asm volatile("cp.async.cg.shared.global [%0], [%1], 16, %2;"
                 :: "r"(dst), "l"(src), "r"(szbytes) : "memory");
}
#define CP_COMMIT() asm volatile("cp.async.commit_group;" ::: "memory")
#define CP_WAIT0()  asm volatile("cp.async.wait_group 0;" ::: "memory")

// ---------------------------------------------------------------------------
// Pass 1: per (b,t) tile U = c . t^T [32 x 64], fused softmax(l)/max(c)/sum(l)
// -> g_scores[b*T+t]. One warp per tile, 4 tiles per 128-thread block.
//
// SMEM is TOKEN-MAJOR (row = token, 32 k per chunk) with an XOR swizzle on the
// 4-float k-group:  phys = row*32 + (4*kg ^ swz(row)*4) + (k&3)
//   B rows: swz = (l>>3)&7  -> compute load j (rows 8*lg+j) sees 8 distinct
//           offsets 4kg^4lg = all 32 banks -> conflict-free, 1 wavefront.
//   A rows: swz = (c>>3)&3  -> compute load i sees 4 distinct offsets,
//           broadcast to 8 lanes each -> conflict-free.
// Token-major staging is contiguous 16B -> cp.async (no transpose STS at all),
// double-buffered so chunk n+1 loads overlap chunk n compute.
// ---------------------------------------------------------------------------
#define SB_STAGE 8192    /* floats per stage: 4 tiles * 64 l * 32 k */
#define SA_STAGE 1024    /* floats per stage: 32 c * 32 k */
#define DYN_FLOATS (2 * SB_STAGE + 2 * SA_STAGE)
#define DYN_BYTES  (DYN_FLOATS * 4)

__global__ __launch_bounds__(128, 3)
void scores_kernel(const int* __restrict__ claim,
                   const int* __restrict__ targets,
                   const float* __restrict__ emb)
{
    extern __shared__ float dynsmem[];
    float* SB = dynsmem;                    // [2][4][64][32] swizzled
    float* SA = dynsmem + 2 * SB_STAGE;     // [2][32][32]    swizzled
    __shared__ int s_cid[LC];
    __shared__ int s_tid[4 * LT];

    const int b      = blockIdx.y;
    const int t_base = blockIdx.x * 4;
    const int tid    = threadIdx.x;
    const int warp   = tid >> 5;
    const int lane   = tid & 31;
    const int cg     = lane >> 3;       // c0 = 8*cg
    const int lg     = lane & 7;        // l0 = 8*lg

    if (tid < LC) s_cid[tid] = claim[b * LC + tid];
    for (int u = tid; u < 4 * LT; u += 128) {
        int tt = u >> 6, l = u & 63;
        s_tid[u] = targets[((size_t)b * TT + (t_base + tt)) * LT + l];
    }
    __syncthreads();

    // -------- staging (cp.async, one commit group per chunk) --------
    auto stage = [&](int chunk) {
        const int k0    = chunk * 32;
        const int kmax4 = (chunk == 9) ? 3 : 8;   // valid float4s (300 = 9*32+12)
        const int st    = chunk & 1;
        float* sBs = SB + st * SB_STAGE;
        float* sAs = SA + st * SA_STAGE;
#pragma unroll
        for (int it = 0; it < 16; ++it) {          // sB: 2048 float4 units
            int u = it * 128 + tid;
            int lr = u >> 3, q = u & 7, l = lr & 63;
            const float* src = emb + (size_t)s_tid[lr] * D + k0 + 4 * q;
            unsigned dst = smem_u32(sBs + (lr >> 6) * 2048 + l * 32 +
                                    ((4 * q) ^ (((l >> 3) & 7) << 2)));
            int ok = (q < kmax4);
            cp16(dst, ok ? src : emb, ok ? 16 : 0);
        }
#pragma unroll
        for (int it = 0; it < 2; ++it) {           // sA: 256 float4 units
            int u = it * 128 + tid;
            int c = u >> 3, q = u & 7;
            const float* src = emb + (size_t)s_cid[c] * D + k0 + 4 * q;
            unsigned dst = smem_u32(sAs + c * 32 +
                                    ((4 * q) ^ (((c >> 3) & 3) << 2)));
            int ok = (q < kmax4);
            cp16(dst, ok ? src : emb, ok ? 16 : 0);
        }
        CP_COMMIT();
    };

    unsigned long long acc2[8][4];   // [c_i][l_pair] packed {l even, l odd}
#pragma unroll
    for (int i = 0; i < 8; ++i)
#pragma unroll
        for (int j = 0; j < 4; ++j) acc2[i][j] = 0ull;

    stage(0);

    for (int chunk = 0; chunk < 10; ++chunk) {
        CP_WAIT0();            // this chunk's data arrived (mine)
        __syncthreads();       // everyone's data visible; prev buffer free
        if (chunk < 9) stage(chunk + 1);   // overlaps with compute below

        const float* Bw = SB + (chunk & 1) * SB_STAGE + warp * 2048;
        const float* Aw = SA + (chunk & 1) * SA_STAGE;

#pragma unroll
        for (int kg = 0; kg < 8; ++kg) {
            const int kc = 4 * kg;
            float4 bv[8];
#pragma unroll
            for (int j = 0; j < 8; ++j)
                bv[j] = *(const float4*)&Bw[(8 * lg + j) * 32 + (kc ^ (lg << 2))];
            unsigned long long bp[4][4];
#pragma unroll
            for (int jp = 0; jp < 4; ++jp) {
                bp[jp][0] = pack2(bv[2 * jp].x, bv[2 * jp + 1].x);
                bp[jp][1] = pack2(bv[2 * jp].y, bv[2 * jp + 1].y);
                bp[jp][2] = pack2(bv[2 * jp].z, bv[2 * jp + 1].z);
                bp[jp][3] = pack2(bv[2 * jp].w, bv[2 * jp + 1].w);
            }
#pragma unroll
            for (int i = 0; i < 8; ++i) {
                float4 av = *(const float4*)&Aw[(8 * cg + i) * 32 + (kc ^ (cg << 2))];
                unsigned long long a0 = pack2(av.x, av.x);
                unsigned long long a1 = pack2(av.y, av.y);
                unsigned long long a2 = pack2(av.z, av.z);
                unsigned long long a3 = pack2(av.w, av.w);
#pragma unroll
                for (int jp = 0; jp < 4; ++jp) {
                    ffma2(acc2[i][jp], a0, bp[jp][0]);
                    ffma2(acc2[i][jp], a1, bp[jp][1]);
                    ffma2(acc2[i][jp], a2, bp[jp][2]);
                    ffma2(acc2[i][jp], a3, bp[jp][3]);
                }
            }
        }
    }

    // Unpack accumulators to scalar fragment acc[8][8] (l = l0 + j)
    float acc[8][8];
#pragma unroll
    for (int i = 0; i < 8; ++i)
#pragma unroll
        for (int jp = 0; jp < 4; ++jp)
            unpack2(acc2[i][jp], acc[i][2 * jp], acc[i][2 * jp + 1]);

    // Row stats per c (softmax over all 64 l): 8-lane lg-groups share a row.
    float rinv[8];
#pragma unroll
    for (int i = 0; i < 8; ++i) {
        float m = acc[i][0];
#pragma unroll
        for (int j = 1; j < 8; ++j) m = fmaxf(m, acc[i][j]);
        m = fmaxf(m, __shfl_xor_sync(0xffffffffu, m, 1));
        m = fmaxf(m, __shfl_xor_sync(0xffffffffu, m, 2));
        m = fmaxf(m, __shfl_xor_sync(0xffffffffu, m, 4));
        float s = 0.f;
#pragma unroll
        for (int j = 0; j < 8; ++j) {
            acc[i][j] = __expf(acc[i][j] - m);
            s += acc[i][j];
        }
        s += __shfl_xor_sync(0xffffffffu, s, 1);
        s += __shfl_xor_sync(0xffffffffu, s, 2);
        s += __shfl_xor_sync(0xffffffffu, s, 4);
        rinv[i] = 1.0f / s;
    }

    // Column max over all 32 c (cross-cg via xor 8,16), then sum over 64 l.
    float colsum = 0.f;
#pragma unroll
    for (int j = 0; j < 8; ++j) {
        float cm = acc[0][j] * rinv[0];
#pragma unroll
        for (int i = 1; i < 8; ++i) cm = fmaxf(cm, acc[i][j] * rinv[i]);
        cm = fmaxf(cm, __shfl_xor_sync(0xffffffffu, cm, 8));
        cm = fmaxf(cm, __shfl_xor_sync(0xffffffffu, cm, 16));
        colsum += cm;
    }
    colsum += __shfl_xor_sync(0xffffffffu, colsum, 1);
    colsum += __shfl_xor_sync(0xffffffffu, colsum, 2);
    colsum += __shfl_xor_sync(0xffffffffu, colsum, 4);

    if (lane == 0) g_scores[b * TT + t_base + warp] = colsum;
}

// ---------------------------------------------------------------------------
// Pass 2: per-b top-5 of 256 scores, sorted descending (ties -> lowest index).
// ---------------------------------------------------------------------------
__global__ void topk_kernel()
{
    const int b    = blockIdx.x;
    const int lane = threadIdx.x;
    float v[8];
#pragma unroll
    for (int j = 0; j < 8; ++j) v[j] = g_scores[b * TT + lane * 8 + j];

    for (int r = 0; r < NSEL; ++r) {
        float bm = v[0];
        int   bi = lane * 8;
#pragma unroll
        for (int j = 1; j < 8; ++j)
            if (v[j] > bm) { bm = v[j]; bi = lane * 8 + j; }
#pragma unroll
        for (int s = 16; s >= 1; s >>= 1) {
            float om = __shfl_xor_sync(0xffffffffu, bm, s);
            int   oi = __shfl_xor_sync(0xffffffffu, bi, s);
            if (om > bm || (om == bm && oi < bi)) { bm = om; bi = oi; }
        }
        if (lane == 0) g_topidx[b * NSEL + r] = bi;
        if ((bi >> 3) == lane) v[bi & 7] = -3.402823466e38f;
    }
}

// ---------------------------------------------------------------------------
// Pass 3: recompute U for the 5 selected t per b, L2-normalize each c-row
// over l, write [B,5,32,64]. ~1% of pass-1 work; kept simple (passed R5).
// ---------------------------------------------------------------------------
__global__ __launch_bounds__(160, 2)
void output_kernel(const int* __restrict__ claim,
                   const int* __restrict__ targets,
                   const float* __restrict__ emb,
                   float* __restrict__ out)
{
    __shared__ __align__(16) float sA[32][32];
    __shared__ __align__(16) float sB[NSEL][32][64];
    __shared__ int s_cid[LC];
    __shared__ int s_tid[NSEL * LT];
    __shared__ int s_sel[NSEL];

    const int b    = blockIdx.x;
    const int tid  = threadIdx.x;
    const int warp = tid >> 5;          // 0..4
    const int lane = tid & 31;
    const int cg   = lane >> 3;
    const int lg   = lane & 7;
    const int c0   = cg * 8;
    const int l0   = lg * 8;

    if (tid < NSEL) s_sel[tid] = g_topidx[b * NSEL + tid];
    if (tid < LC)   s_cid[tid] = claim[b * LC + tid];
    __syncthreads();
    for (int u = tid; u < NSEL * LT; u += 160) {
        int tt = u >> 6, l = u & 63;
        s_tid[u] = targets[((size_t)b * TT + s_sel[tt]) * LT + l];
    }
    __syncthreads();

    float acc[8][8];
#pragma unroll
    for (int i = 0; i < 8; ++i)
#pragma unroll
        for (int j = 0; j < 8; ++j) acc[i][j] = 0.f;

    const float4 zero4 = make_float4(0.f, 0.f, 0.f, 0.f);

    for (int chunk = 0; chunk < 10; ++chunk) {
        const int k0    = chunk * 32;
        const int kmax4 = (D - k0 + 3) >> 2;
        __syncthreads();

        for (int u = tid; u < 256; u += 160) {
            int c = u >> 3, q = u & 7;
            const float4* p = (const float4*)(emb + (size_t)s_cid[c] * D + k0) + q;
            float4 v = (q < kmax4) ? __ldg(p) : zero4;
            sA[q * 4 + 0][c] = v.x;
            sA[q * 4 + 1][c] = v.y;
            sA[q * 4 + 2][c] = v.z;
            sA[q * 4 + 3][c] = v.w;
        }
        for (int u = tid; u < NSEL * LT * 8; u += 160) {
            int lr = u >> 3, q = u & 7;
            const float4* p = (const float4*)(emb + (size_t)s_tid[lr] * D + k0) + q;
            float4 v = (q < kmax4) ? __ldg(p) : zero4;
            float* dst = &sB[lr >> 6][q * 4][lr & 63];
            dst[0 * 64] = v.x;
            dst[1 * 64] = v.y;
            dst[2 * 64] = v.z;
            dst[3 * 64] = v.w;
        }
        __syncthreads();

        const float (*Bw)[64] = sB[warp];
#pragma unroll 4
        for (int kk = 0; kk < 32; ++kk) {
            float4 a0 = *(const float4*)&sA[kk][c0];
            float4 a1 = *(const float4*)&sA[kk][c0 + 4];
            float4 b0 = *(const float4*)&Bw[kk][l0];
            float4 b1 = *(const float4*)&Bw[kk][l0 + 4];
            float av[8] = {a0.x, a0.y, a0.z, a0.w, a1.x, a1.y, a1.z, a1.w};
            float bv[8] = {b0.x, b0.y, b0.z, b0.w, b1.x, b1.y, b1.z, b1.w};
#pragma unroll
            for (int i = 0; i < 8; ++i)
#pragma unroll
                for (int j = 0; j < 8; ++j)
                    acc[i][j] = fmaf(av[i], bv[j], acc[i][j]);
        }
    }

#pragma unroll
    for (int i = 0; i < 8; ++i) {
        float s2 = 0.f;
#pragma unroll
        for (int j = 0; j < 8; ++j) s2 = fmaf(acc[i][j], acc[i][j], s2);
        s2 += __shfl_xor_sync(0xffffffffu, s2, 1);
        s2 += __shfl_xor_sync(0xffffffffu, s2, 2);
        s2 += __shfl_xor_sync(0xffffffffu, s2, 4);
        float inv = 1.0f / sqrtf(s2);

        size_t off = (((size_t)(b * NSEL + warp) * LC) + (c0 + i)) * LT + l0;
        float4 v0 = make_float4(acc[i][0] * inv, acc[i][1] * inv,
                                acc[i][2] * inv, acc[i][3] * inv);
        float4 v1 = make_float4(acc[i][4] * inv, acc[i][5] * inv,
                                acc[i][6] * inv, acc[i][7] * inv);
        *(float4*)(out + off)     = v0;
        *(float4*)(out + off + 4) = v1;
    }
}

// ---------------------------------------------------------------------------
extern "C" void kernel_launch(void* const* d_in, const int* in_sizes, int n_in,
                              void* d_out, int out_size)
{
    const int*   claim   = nullptr;
    const int*   targets = nullptr;
    const float* emb     = nullptr;
    for (int i = 0; i < n_in; ++i) {
        if (in_sizes[i] == BATCH * LC)            claim   = (const int*)d_in[i];
        else if (in_sizes[i] == BATCH * TT * LT)  targets = (const int*)d_in[i];
        else if (in_sizes[i] == VOCAB * D)        emb     = (const float*)d_in[i];
        // n (size 1) is the compile-time constant NSEL=5; ignored.
    }
    float* out = (float*)d_out;

    // Opt into >48KB dynamic shared for the pipelined GEMM (idempotent; not an
    // allocation and not a stream sync, so graph-capture safe).
    cudaFuncSetAttribute(scores_kernel,
                         cudaFuncAttributeMaxDynamicSharedMemorySize, DYN_BYTES);

    scores_kernel<<<dim3(TT / 4, BATCH, 1), 128, DYN_BYTES>>>(claim, targets, emb);
    topk_kernel<<<BATCH, 32>>>();
    output_kernel<<<BATCH, 160>>>(claim, targets, emb, out);
}

// round 12
// speedup vs baseline: 1.3100x; 1.3100x over previous
#include <cuda_runtime.h>
#include <cstdint>
#include <cstddef>

// Problem constants (fixed by the dataset generator)
#define VOCAB 50000
#define D     300
#define BATCH 64
#define LC    32
#define TT    256
#define LT    64
#define NSEL  5

// Scratch (no allocations allowed -> device globals)
__device__ float g_scores[BATCH * TT];
__device__ int   g_topidx[BATCH * NSEL];

// ---------------------------------------------------------------------------
// Helpers: f32x2 packed FMA (sm_103a FFMA2, PTX-only) and cp.async
// ---------------------------------------------------------------------------
__device__ __forceinline__ void unpack2(unsigned long long v, float& x, float& y) {
    asm("mov.b64 {%0, %1}, %2;" : "=f"(x), "=f"(y) : "l"(v));
}
__device__ __forceinline__ void ffma2(unsigned long long& d,
                                      unsigned long long a,
                                      unsigned long long b) {
    asm("fma.rn.f32x2 %0, %1, %2, %0;" : "+l"(d) : "l"(a), "l"(b));
}
__device__ __forceinline__ unsigned smem_u32(const void* p) {
    return (unsigned)__cvta_generic_to_shared(p);
}
__device__ __forceinline__ void cp16(unsigned dst, const float* src, int szbytes) {
    asm volatile("cp.async.cg.shared.global [%0], [%1], 16, %2;"
                 :: "r"(dst), "l"(src), "r"(szbytes) : "memory");
}
#define CP_COMMIT() asm volatile("cp.async.commit_group;" ::: "memory")
#define CP_WAIT0()  asm volatile("cp.async.wait_group 0;" ::: "memory")

// ---------------------------------------------------------------------------
// Pass 1: per (b,t) tile U = c . t^T [32 x 64], fused softmax(l)/max(c)/sum(l)
// -> g_scores[b*T+t]. 256-thread block = 4 tiles; TWO warps per tile (each
// warp computes a 32c x 32l half). Per-lane fragment: 8c x 4l, with each
// accumulator a packed f32x2 holding {sum over even k, sum over odd k} --
// both FFMA2 operands are adjacent-k pairs read DIRECTLY from token-major
// LDS.128 loads (no packing movs, no transpose staging; halves summed once
// in the epilogue).
//
// SMEM token-major, XOR-swizzled on the 4-float k-group:
//   B: phys = l*32 + (4q ^ (((l>>2)&7)<<2)) + (k&3)
//      compute lane (cg=lane>>3, lg=lane&7) loads rows lhalf+4*lg+j; swizzle
//      = lg for all j -> col = kc ^ (lg<<2): 8 distinct 16B groups = 32 banks,
//      4-way broadcast over cg -> conflict-free; j-stride = immediate 128B.
//   A: phys = c*32 + (4q ^ (((c>>3)&3)<<2)) + (k&3)
//      rows 8*cg+i -> col = kc ^ (cg<<2): 4 distinct groups, 8-way broadcast
//      -> conflict-free; i-stride immediate.
// Addresses: ONE LOP3 per operand per kg; everything else immediate offsets.
// ---------------------------------------------------------------------------
#define SB_STAGE 8192    /* floats per stage: 4 tiles * 64 l * 32 k */
#define SA_STAGE 1024    /* floats per stage: 32 c * 32 k */
#define DYN_BYTES ((2 * SB_STAGE + 2 * SA_STAGE) * 4)

__global__ __launch_bounds__(256, 2)
void scores_kernel(const int* __restrict__ claim,
                   const int* __restrict__ targets,
                   const float* __restrict__ emb)
{
    extern __shared__ float dynsmem[];
    float* SB = dynsmem;                    // [2][4 tiles][64 l][32 k] swizzled
    float* SA = dynsmem + 2 * SB_STAGE;     // [2][32 c][32 k]          swizzled
    __shared__ int   s_cid[LC];
    __shared__ int   s_tid[4 * LT];
    __shared__ float sRowMax[8][32];
    __shared__ float sRowSum[8][32];
    __shared__ float sPart[8];

    const int b      = blockIdx.y;
    const int t_base = blockIdx.x * 4;
    const int tid    = threadIdx.x;
    const int warp   = tid >> 5;        // 0..7
    const int lane   = tid & 31;
    const int cg     = lane >> 3;       // c0 = 8*cg
    const int lg     = lane & 7;
    const int tile   = warp >> 1;       // 0..3
    const int lhalf  = (warp & 1) * 32; // which 32-l half of the tile

    if (tid < LC) s_cid[tid] = claim[b * LC + tid];
    if (tid < 4 * LT) {
        int tt = tid >> 6, l = tid & 63;
        s_tid[tid] = targets[((size_t)b * TT + (t_base + tt)) * LT + l];
    }
    __syncthreads();

    // -------- staging (cp.async token-major + swizzle, one group/chunk) ----
    auto stage = [&](int chunk) {
        const int k0    = chunk * 32;
        const int kmax4 = (chunk == 9) ? 3 : 8;   // 300 = 9*32 + 12
        const int st    = chunk & 1;
        float* sBs = SB + st * SB_STAGE;
        float* sAs = SA + st * SA_STAGE;
#pragma unroll
        for (int it = 0; it < 8; ++it) {           // sB: 2048 float4 units
            int u = it * 256 + tid;
            int lr = u >> 3, q = u & 7, l = lr & 63;
            const float* src = emb + (size_t)s_tid[lr] * D + k0 + 4 * q;
            unsigned dst = smem_u32(sBs + (lr >> 6) * 2048 + l * 32 +
                                    ((4 * q) ^ (((l >> 2) & 7) << 2)));
            int ok = (q < kmax4);
            cp16(dst, ok ? src : emb, ok ? 16 : 0);   // size 0 -> zero-fill
        }
        {                                           // sA: 256 float4 units
            int c = tid >> 3, q = tid & 7;
            const float* src = emb + (size_t)s_cid[c] * D + k0 + 4 * q;
            unsigned dst = smem_u32(sAs + c * 32 +
                                    ((4 * q) ^ (((c >> 3) & 3) << 2)));
            int ok = (q < kmax4);
            cp16(dst, ok ? src : emb, ok ? 16 : 0);
        }
        CP_COMMIT();
    };

    unsigned long long acc2[8][4];   // [c_i][l_j] = {sum even k, sum odd k}
#pragma unroll
    for (int i = 0; i < 8; ++i)
#pragma unroll
        for (int j = 0; j < 4; ++j) acc2[i][j] = 0ull;

    stage(0);

    for (int chunk = 0; chunk < 10; ++chunk) {
        CP_WAIT0();
        __syncthreads();
        if (chunk < 9) stage(chunk + 1);   // overlaps compute below

        const float* Bw = SB + (chunk & 1) * SB_STAGE + tile * 2048
                             + (lhalf + 4 * lg) * 32;
        const float* Aw = SA + (chunk & 1) * SA_STAGE + (8 * cg) * 32;
        const int bsw = lg << 2;   // B swizzle group for this lane
        const int asw = cg << 2;   // A swizzle group for this lane

#pragma unroll
        for (int kg = 0; kg < 8; ++kg) {
            const int kc = 4 * kg;
            // 4 l rows x 4 k : direct 64-bit k-pairs
            ulonglong2 bv[4];
#pragma unroll
            for (int j = 0; j < 4; ++j)
                bv[j] = *(const ulonglong2*)&Bw[j * 32 + (kc ^ bsw)];
#pragma unroll
            for (int i = 0; i < 8; ++i) {
                ulonglong2 av = *(const ulonglong2*)&Aw[i * 32 + (kc ^ asw)];
#pragma unroll
                for (int j = 0; j < 4; ++j) ffma2(acc2[i][j], av.x, bv[j].x);
#pragma unroll
                for (int j = 0; j < 4; ++j) ffma2(acc2[i][j], av.y, bv[j].y);
            }
        }
    }

    // Merge k-parity halves: U[c0+i][lhalf + 4*lg + j]
    float acc[8][4];
#pragma unroll
    for (int i = 0; i < 8; ++i)
#pragma unroll
        for (int j = 0; j < 4; ++j) {
            float lo, hi;
            unpack2(acc2[i][j], lo, hi);
            acc[i][j] = lo + hi;
        }

    // ---- softmax over l (64, spans warp pair) / max over c / sum over l ----
    // Row max within warp (32 l): over j then lg (xor 1,2,4).
#pragma unroll
    for (int i = 0; i < 8; ++i) {
        float m = fmaxf(fmaxf(acc[i][0], acc[i][1]), fmaxf(acc[i][2], acc[i][3]));
        m = fmaxf(m, __shfl_xor_sync(0xffffffffu, m, 1));
        m = fmaxf(m, __shfl_xor_sync(0xffffffffu, m, 2));
        m = fmaxf(m, __shfl_xor_sync(0xffffffffu, m, 4));
        if (lg == 0) sRowMax[warp][8 * cg + i] = m;
    }
    __syncthreads();

    float rinv[8];
#pragma unroll
    for (int i = 0; i < 8; ++i) {
        float m2 = fmaxf(sRowMax[warp][8 * cg + i], sRowMax[warp ^ 1][8 * cg + i]);
        float s = 0.f;
#pragma unroll
        for (int j = 0; j < 4; ++j) {
            acc[i][j] = __expf(acc[i][j] - m2);
            s += acc[i][j];
        }
        s += __shfl_xor_sync(0xffffffffu, s, 1);
        s += __shfl_xor_sync(0xffffffffu, s, 2);
        s += __shfl_xor_sync(0xffffffffu, s, 4);
        if (lg == 0) sRowSum[warp][8 * cg + i] = s;
    }
    __syncthreads();
#pragma unroll
    for (int i = 0; i < 8; ++i)
        rinv[i] = 1.0f / (sRowSum[warp][8 * cg + i] + sRowSum[warp ^ 1][8 * cg + i]);

    // Column max over all 32 c (i in-lane, cg via xor 8,16), sum over this
    // warp's 32 l, then combine the warp pair.
    float colsum = 0.f;
#pragma unroll
    for (int j = 0; j < 4; ++j) {
        float cm = acc[0][j] * rinv[0];
#pragma unroll
        for (int i = 1; i < 8; ++i) cm = fmaxf(cm, acc[i][j] * rinv[i]);
        cm = fmaxf(cm, __shfl_xor_sync(0xffffffffu, cm, 8));
        cm = fmaxf(cm, __shfl_xor_sync(0xffffffffu, cm, 16));
        colsum += cm;
    }
    colsum += __shfl_xor_sync(0xffffffffu, colsum, 1);
    colsum += __shfl_xor_sync(0xffffffffu, colsum, 2);
    colsum += __shfl_xor_sync(0xffffffffu, colsum, 4);
    if (lane == 0) sPart[warp] = colsum;
    __syncthreads();
    if ((warp & 1) == 0 && lane == 0)
        g_scores[b * TT + t_base + tile] = sPart[warp] + sPart[warp + 1];
}

// ---------------------------------------------------------------------------
// Pass 2: per-b top-5 of 256 scores, sorted descending (ties -> lowest index).
// ---------------------------------------------------------------------------
__global__ void topk_kernel()
{
    const int b    = blockIdx.x;
    const int lane = threadIdx.x;
    float v[8];
#pragma unroll
    for (int j = 0; j < 8; ++j) v[j] = g_scores[b * TT + lane * 8 + j];

    for (int r = 0; r < NSEL; ++r) {
        float bm = v[0];
        int   bi = lane * 8;
#pragma unroll
        for (int j = 1; j < 8; ++j)
            if (v[j] > bm) { bm = v[j]; bi = lane * 8 + j; }
#pragma unroll
        for (int s = 16; s >= 1; s >>= 1) {
            float om = __shfl_xor_sync(0xffffffffu, bm, s);
            int   oi = __shfl_xor_sync(0xffffffffu, bi, s);
            if (om > bm || (om == bm && oi < bi)) { bm = om; bi = oi; }
        }
        if (lane == 0) g_topidx[b * NSEL + r] = bi;
        if ((bi >> 3) == lane) v[bi & 7] = -3.402823466e38f;
    }
}

// ---------------------------------------------------------------------------
// Pass 3: recompute U for the 5 selected t per b, L2-normalize each c-row
// over l, write [B,5,32,64]. ~1% of pass-1 work; proven-correct R5 version.
// ---------------------------------------------------------------------------
__global__ __launch_bounds__(160, 2)
void output_kernel(const int* __restrict__ claim,
                   const int* __restrict__ targets,
                   const float* __restrict__ emb,
                   float* __restrict__ out)
{
    __shared__ __align__(16) float sA[32][32];
    __shared__ __align__(16) float sB[NSEL][32][64];
    __shared__ int s_cid[LC];
    __shared__ int s_tid[NSEL * LT];
    __shared__ int s_sel[NSEL];

    const int b    = blockIdx.x;
    const int tid  = threadIdx.x;
    const int warp = tid >> 5;          // 0..4
    const int lane = tid & 31;
    const int cg   = lane >> 3;
    const int lg   = lane & 7;
    const int c0   = cg * 8;
    const int l0   = lg * 8;

    if (tid < NSEL) s_sel[tid] = g_topidx[b * NSEL + tid];
    if (tid < LC)   s_cid[tid] = claim[b * LC + tid];
    __syncthreads();
    for (int u = tid; u < NSEL * LT; u += 160) {
        int tt = u >> 6, l = u & 63;
        s_tid[u] = targets[((size_t)b * TT + s_sel[tt]) * LT + l];
    }
    __syncthreads();

    float acc[8][8];
#pragma unroll
    for (int i = 0; i < 8; ++i)
#pragma unroll
        for (int j = 0; j < 8; ++j) acc[i][j] = 0.f;

    const float4 zero4 = make_float4(0.f, 0.f, 0.f, 0.f);

    for (int chunk = 0; chunk < 10; ++chunk) {
        const int k0    = chunk * 32;
        const int kmax4 = (D - k0 + 3) >> 2;
        __syncthreads();

        for (int u = tid; u < 256; u += 160) {
            int c = u >> 3, q = u & 7;
            const float4* p = (const float4*)(emb + (size_t)s_cid[c] * D + k0) + q;
            float4 v = (q < kmax4) ? __ldg(p) : zero4;
            sA[q * 4 + 0][c] = v.x;
            sA[q * 4 + 1][c] = v.y;
            sA[q * 4 + 2][c] = v.z;
            sA[q * 4 + 3][c] = v.w;
        }
        for (int u = tid; u < NSEL * LT * 8; u += 160) {
            int lr = u >> 3, q = u & 7;
            const float4* p = (const float4*)(emb + (size_t)s_tid[lr] * D + k0) + q;
            float4 v = (q < kmax4) ? __ldg(p) : zero4;
            float* dst = &sB[lr >> 6][q * 4][lr & 63];
            dst[0 * 64] = v.x;
            dst[1 * 64] = v.y;
            dst[2 * 64] = v.z;
            dst[3 * 64] = v.w;
        }
        __syncthreads();

        const float (*Bw)[64] = sB[warp];
#pragma unroll 4
        for (int kk = 0; kk < 32; ++kk) {
            float4 a0 = *(const float4*)&sA[kk][c0];
            float4 a1 = *(const float4*)&sA[kk][c0 + 4];
            float4 b0 = *(const float4*)&Bw[kk][l0];
            float4 b1 = *(const float4*)&Bw[kk][l0 + 4];
            float av[8] = {a0.x, a0.y, a0.z, a0.w, a1.x, a1.y, a1.z, a1.w};
            float bv[8] = {b0.x, b0.y, b0.z, b0.w, b1.x, b1.y, b1.z, b1.w};
#pragma unroll
            for (int i = 0; i < 8; ++i)
#pragma unroll
                for (int j = 0; j < 8; ++j)
                    acc[i][j] = fmaf(av[i], bv[j], acc[i][j]);
        }
    }

#pragma unroll
    for (int i = 0; i < 8; ++i) {
        float s2 = 0.f;
#pragma unroll
        for (int j = 0; j < 8; ++j) s2 = fmaf(acc[i][j], acc[i][j], s2);
        s2 += __shfl_xor_sync(0xffffffffu, s2, 1);
        s2 += __shfl_xor_sync(0xffffffffu, s2, 2);
        s2 += __shfl_xor_sync(0xffffffffu, s2, 4);
        float inv = 1.0f / sqrtf(s2);

        size_t off = (((size_t)(b * NSEL + warp) * LC) + (c0 + i)) * LT + l0;
        float4 v0 = make_float4(acc[i][0] * inv, acc[i][1] * inv,
                                acc[i][2] * inv, acc[i][3] * inv);
        float4 v1 = make_float4(acc[i][4] * inv, acc[i][5] * inv,
                                acc[i][6] * inv, acc[i][7] * inv);
        *(float4*)(out + off)     = v0;
        *(float4*)(out + off + 4) = v1;
    }
}

// ---------------------------------------------------------------------------
extern "C" void kernel_launch(void* const* d_in, const int* in_sizes, int n_in,
                              void* d_out, int out_size)
{
    const int*   claim   = nullptr;
    const int*   targets = nullptr;
    const float* emb     = nullptr;
    for (int i = 0; i < n_in; ++i) {
        if (in_sizes[i] == BATCH * LC)            claim   = (const int*)d_in[i];
        else if (in_sizes[i] == BATCH * TT * LT)  targets = (const int*)d_in[i];
        else if (in_sizes[i] == VOCAB * D)        emb     = (const float*)d_in[i];
        // n (size 1) is the compile-time constant NSEL=5; ignored.
    }
    float* out = (float*)d_out;

    cudaFuncSetAttribute(scores_kernel,
                         cudaFuncAttributeMaxDynamicSharedMemorySize, DYN_BYTES);

    scores_kernel<<<dim3(TT / 4, BATCH, 1), 256, DYN_BYTES>>>(claim, targets, emb);
    topk_kernel<<<BATCH, 32>>>();
    output_kernel<<<BATCH, 160>>>(claim, targets, emb, out);
}

// round 14
// speedup vs baseline: 1.3698x; 1.0457x over previous
#include <cuda_runtime.h>
#include <cstdint>
#include <cstddef>

// Problem constants (fixed by the dataset generator)
#define VOCAB 50000
#define D     300
#define BATCH 64
#define LC    32
#define TT    256
#define LT    64
#define NSEL  5

// Scratch (no allocations allowed -> device globals)
__device__ float g_scores[BATCH * TT];
__device__ int   g_topidx[BATCH * NSEL];

// ---------------------------------------------------------------------------
// Helpers: f32x2 packed FMA (sm_103a FFMA2, PTX-only) and cp.async
// ---------------------------------------------------------------------------
__device__ __forceinline__ void unpack2(unsigned long long v, float& x, float& y) {
    asm("mov.b64 {%0, %1}, %2;" : "=f"(x), "=f"(y) : "l"(v));
}
__device__ __forceinline__ void ffma2(unsigned long long& d,
                                      unsigned long long a,
                                      unsigned long long b) {
    asm("fma.rn.f32x2 %0, %1, %2, %0;" : "+l"(d) : "l"(a), "l"(b));
}
__device__ __forceinline__ unsigned smem_u32(const void* p) {
    return (unsigned)__cvta_generic_to_shared(p);
}
__device__ __forceinline__ void cp16(unsigned dst, const float* src, int szbytes) {
    asm volatile("cp.async.cg.shared.global [%0], [%1], 16, %2;"
                 :: "r"(dst), "l"(src), "r"(szbytes) : "memory");
}
#define CP_COMMIT() asm volatile("cp.async.commit_group;" ::: "memory")
#define CP_WAIT0()  asm volatile("cp.async.wait_group 0;" ::: "memory")

// ---------------------------------------------------------------------------
// Pass 1: per (b,t) tile U = c . t^T [32 x 64], fused softmax(l)/max(c)/sum(l)
// -> g_scores[b*T+t].
// 128-thread block = 2 tiles (two warps per tile, 32c x 32l half each).
// __launch_bounds__(128,3) -> 170-reg budget (R11 pinned at the 128 cap ->
// no load hoisting / possible spills; fma pipe idled at 52%). All 12 LDS.128
// of each kg are batched up front (MLP=12) before the 64 FFMA2s.
// Per-lane fragment: 8c x 4l; each accumulator is f32x2 {sum even k, sum odd
// k} so BOTH FFMA2 operands come straight from token-major LDS.128 halves --
// zero packing instructions (validated R11: alu 59%->13%).
//
// SMEM token-major, XOR-swizzled on the 4-float k-group (validated R11):
//   B: phys = l*32 + (4q ^ (((l>>2)&7)<<2)) + (k&3)   -> conflict-free
//   A: phys = c*32 + (4q ^ (((c>>3)&3)<<2)) + (k&3)   -> conflict-free
// ---------------------------------------------------------------------------
#define SB_STAGE 4096    /* floats per stage: 2 tiles * 64 l * 32 k */
#define SA_STAGE 1024    /* floats per stage: 32 c * 32 k */
#define DYN_BYTES ((2 * SB_STAGE + 2 * SA_STAGE) * 4)

__global__ __launch_bounds__(128, 3)
void scores_kernel(const int* __restrict__ claim,
                   const int* __restrict__ targets,
                   const float* __restrict__ emb)
{
    extern __shared__ float dynsmem[];
    float* SB = dynsmem;                    // [2][2 tiles][64 l][32 k] swizzled
    float* SA = dynsmem + 2 * SB_STAGE;     // [2][32 c][32 k]          swizzled
    __shared__ int   s_cid[LC];
    __shared__ int   s_tid[2 * LT];
    __shared__ float sRowMax[4][32];
    __shared__ float sRowSum[4][32];
    __shared__ float sPart[4];

    const int b      = blockIdx.y;
    const int t_base = blockIdx.x * 2;
    const int tid    = threadIdx.x;
    const int warp   = tid >> 5;        // 0..3
    const int lane   = tid & 31;
    const int cg     = lane >> 3;       // c0 = 8*cg
    const int lg     = lane & 7;
    const int tile   = warp >> 1;       // 0..1
    const int lhalf  = (warp & 1) * 32; // which 32-l half of the tile

    if (tid < LC) s_cid[tid] = claim[b * LC + tid];
    if (tid < 2 * LT) {
        int tt = tid >> 6, l = tid & 63;
        s_tid[tid] = targets[((size_t)b * TT + (t_base + tt)) * LT + l];
    }
    __syncthreads();

    // -------- staging (cp.async token-major + swizzle, one group/chunk) ----
    auto stage = [&](int chunk) {
        const int k0    = chunk * 32;
        const int kmax4 = (chunk == 9) ? 3 : 8;   // 300 = 9*32 + 12
        const int st    = chunk & 1;
        float* sBs = SB + st * SB_STAGE;
        float* sAs = SA + st * SA_STAGE;
#pragma unroll
        for (int it = 0; it < 8; ++it) {           // sB: 1024 float4 units
            int u = it * 128 + tid;
            int lr = u >> 3, q = u & 7, l = lr & 63;
            const float* src = emb + (size_t)s_tid[lr] * D + k0 + 4 * q;
            unsigned dst = smem_u32(sBs + (lr >> 6) * 2048 + l * 32 +
                                    ((4 * q) ^ (((l >> 2) & 7) << 2)));
            int ok = (q < kmax4);
            cp16(dst, ok ? src : emb, ok ? 16 : 0);   // size 0 -> zero-fill
        }
#pragma unroll
        for (int it = 0; it < 2; ++it) {           // sA: 256 float4 units
            int u = it * 128 + tid;
            int c = u >> 3, q = u & 7;
            const float* src = emb + (size_t)s_cid[c] * D + k0 + 4 * q;
            unsigned dst = smem_u32(sAs + c * 32 +
                                    ((4 * q) ^ (((c >> 3) & 3) << 2)));
            int ok = (q < kmax4);
            cp16(dst, ok ? src : emb, ok ? 16 : 0);
        }
        CP_COMMIT();
    };

    unsigned long long acc2[8][4];   // [c_i][l_j] = {sum even k, sum odd k}
#pragma unroll
    for (int i = 0; i < 8; ++i)
#pragma unroll
        for (int j = 0; j < 4; ++j) acc2[i][j] = 0ull;

    stage(0);

    for (int chunk = 0; chunk < 10; ++chunk) {
        CP_WAIT0();
        __syncthreads();
        if (chunk < 9) stage(chunk + 1);   // overlaps compute below

        const float* Bw = SB + (chunk & 1) * SB_STAGE + tile * 2048
                             + (lhalf + 4 * lg) * 32;
        const float* Aw = SA + (chunk & 1) * SA_STAGE + (8 * cg) * 32;
        const int bsw = lg << 2;   // B swizzle group for this lane
        const int asw = cg << 2;   // A swizzle group for this lane

#pragma unroll
        for (int kg = 0; kg < 8; ++kg) {
            const int kc = 4 * kg;
            // Batch ALL loads for this kg first (MLP=12), then the 64 FFMA2s.
            ulonglong2 bv[4];
#pragma unroll
            for (int j = 0; j < 4; ++j)
                bv[j] = *(const ulonglong2*)&Bw[j * 32 + (kc ^ bsw)];
            ulonglong2 av[8];
#pragma unroll
            for (int i = 0; i < 8; ++i)
                av[i] = *(const ulonglong2*)&Aw[i * 32 + (kc ^ asw)];
#pragma unroll
            for (int i = 0; i < 8; ++i) {
#pragma unroll
                for (int j = 0; j < 4; ++j) ffma2(acc2[i][j], av[i].x, bv[j].x);
#pragma unroll
                for (int j = 0; j < 4; ++j) ffma2(acc2[i][j], av[i].y, bv[j].y);
            }
        }
    }

    // Merge k-parity halves: U[c0+i][lhalf + 4*lg + j]
    float acc[8][4];
#pragma unroll
    for (int i = 0; i < 8; ++i)
#pragma unroll
        for (int j = 0; j < 4; ++j) {
            float lo, hi;
            unpack2(acc2[i][j], lo, hi);
            acc[i][j] = lo + hi;
        }

    // ---- softmax over l (64, spans warp pair) / max over c / sum over l ----
#pragma unroll
    for (int i = 0; i < 8; ++i) {
        float m = fmaxf(fmaxf(acc[i][0], acc[i][1]), fmaxf(acc[i][2], acc[i][3]));
        m = fmaxf(m, __shfl_xor_sync(0xffffffffu, m, 1));
        m = fmaxf(m, __shfl_xor_sync(0xffffffffu, m, 2));
        m = fmaxf(m, __shfl_xor_sync(0xffffffffu, m, 4));
        if (lg == 0) sRowMax[warp][8 * cg + i] = m;
    }
    __syncthreads();

    float rinv[8];
#pragma unroll
    for (int i = 0; i < 8; ++i) {
        float m2 = fmaxf(sRowMax[warp][8 * cg + i], sRowMax[warp ^ 1][8 * cg + i]);
        float s = 0.f;
#pragma unroll
        for (int j = 0; j < 4; ++j) {
            acc[i][j] = __expf(acc[i][j] - m2);
            s += acc[i][j];
        }
        s += __shfl_xor_sync(0xffffffffu, s, 1);
        s += __shfl_xor_sync(0xffffffffu, s, 2);
        s += __shfl_xor_sync(0xffffffffu, s, 4);
        if (lg == 0) sRowSum[warp][8 * cg + i] = s;
    }
    __syncthreads();
#pragma unroll
    for (int i = 0; i < 8; ++i)
        rinv[i] = 1.0f / (sRowSum[warp][8 * cg + i] + sRowSum[warp ^ 1][8 * cg + i]);

    // Column max over all 32 c (i in-lane, cg via xor 8,16), sum over this
    // warp's 32 l, then combine the warp pair.
    float colsum = 0.f;
#pragma unroll
    for (int j = 0; j < 4; ++j) {
        float cm = acc[0][j] * rinv[0];
#pragma unroll
        for (int i = 1; i < 8; ++i) cm = fmaxf(cm, acc[i][j] * rinv[i]);
        cm = fmaxf(cm, __shfl_xor_sync(0xffffffffu, cm, 8));
        cm = fmaxf(cm, __shfl_xor_sync(0xffffffffu, cm, 16));
        colsum += cm;
    }
    colsum += __shfl_xor_sync(0xffffffffu, colsum, 1);
    colsum += __shfl_xor_sync(0xffffffffu, colsum, 2);
    colsum += __shfl_xor_sync(0xffffffffu, colsum, 4);
    if (lane == 0) sPart[warp] = colsum;
    __syncthreads();
    if ((warp & 1) == 0 && lane == 0)
        g_scores[b * TT + t_base + tile] = sPart[warp] + sPart[warp + 1];
}

// ---------------------------------------------------------------------------
// Pass 2: per-b top-5 of 256 scores, sorted descending (ties -> lowest index).
// ---------------------------------------------------------------------------
__global__ void topk_kernel()
{
    const int b    = blockIdx.x;
    const int lane = threadIdx.x;
    float v[8];
#pragma unroll
    for (int j = 0; j < 8; ++j) v[j] = g_scores[b * TT + lane * 8 + j];

    for (int r = 0; r < NSEL; ++r) {
        float bm = v[0];
        int   bi = lane * 8;
#pragma unroll
        for (int j = 1; j < 8; ++j)
            if (v[j] > bm) { bm = v[j]; bi = lane * 8 + j; }
#pragma unroll
        for (int s = 16; s >= 1; s >>= 1) {
            float om = __shfl_xor_sync(0xffffffffu, bm, s);
            int   oi = __shfl_xor_sync(0xffffffffu, bi, s);
            if (om > bm || (om == bm && oi < bi)) { bm = om; bi = oi; }
        }
        if (lane == 0) g_topidx[b * NSEL + r] = bi;
        if ((bi >> 3) == lane) v[bi & 7] = -3.402823466e38f;
    }
}

// ---------------------------------------------------------------------------
// Pass 3: recompute U for the 5 selected t per b, L2-normalize each c-row
// over l, write [B,5,32,64]. ~1% of pass-1 work; proven-correct since R5.
// ---------------------------------------------------------------------------
__global__ __launch_bounds__(160, 2)
void output_kernel(const int* __restrict__ claim,
                   const int* __restrict__ targets,
                   const float* __restrict__ emb,
                   float* __restrict__ out)
{
    __shared__ __align__(16) float sA[32][32];
    __shared__ __align__(16) float sB[NSEL][32][64];
    __shared__ int s_cid[LC];
    __shared__ int s_tid[NSEL * LT];
    __shared__ int s_sel[NSEL];

    const int b    = blockIdx.x;
    const int tid  = threadIdx.x;
    const int warp = tid >> 5;          // 0..4
    const int lane = tid & 31;
    const int cg   = lane >> 3;
    const int lg   = lane & 7;
    const int c0   = cg * 8;
    const int l0   = lg * 8;

    if (tid < NSEL) s_sel[tid] = g_topidx[b * NSEL + tid];
    if (tid < LC)   s_cid[tid] = claim[b * LC + tid];
    __syncthreads();
    for (int u = tid; u < NSEL * LT; u += 160) {
        int tt = u >> 6, l = u & 63;
        s_tid[u] = targets[((size_t)b * TT + s_sel[tt]) * LT + l];
    }
    __syncthreads();

    float acc[8][8];
#pragma unroll
    for (int i = 0; i < 8; ++i)
#pragma unroll
        for (int j = 0; j < 8; ++j) acc[i][j] = 0.f;

    const float4 zero4 = make_float4(0.f, 0.f, 0.f, 0.f);

    for (int chunk = 0; chunk < 10; ++chunk) {
        const int k0    = chunk * 32;
        const int kmax4 = (D - k0 + 3) >> 2;
        __syncthreads();

        for (int u = tid; u < 256; u += 160) {
            int c = u >> 3, q = u & 7;
            const float4* p = (const float4*)(emb + (size_t)s_cid[c] * D + k0) + q;
            float4 v = (q < kmax4) ? __ldg(p) : zero4;
            sA[q * 4 + 0][c] = v.x;
            sA[q * 4 + 1][c] = v.y;
            sA[q * 4 + 2][c] = v.z;
            sA[q * 4 + 3][c] = v.w;
        }
        for (int u = tid; u < NSEL * LT * 8; u += 160) {
            int lr = u >> 3, q = u & 7;
            const float4* p = (const float4*)(emb + (size_t)s_tid[lr] * D + k0) + q;
            float4 v = (q < kmax4) ? __ldg(p) : zero4;
            float* dst = &sB[lr >> 6][q * 4][lr & 63];
            dst[0 * 64] = v.x;
            dst[1 * 64] = v.y;
            dst[2 * 64] = v.z;
            dst[3 * 64] = v.w;
        }
        __syncthreads();

        const float (*Bw)[64] = sB[warp];
#pragma unroll 4
        for (int kk = 0; kk < 32; ++kk) {
            float4 a0 = *(const float4*)&sA[kk][c0];
            float4 a1 = *(const float4*)&sA[kk][c0 + 4];
            float4 b0 = *(const float4*)&Bw[kk][l0];
            float4 b1 = *(const float4*)&Bw[kk][l0 + 4];
            float av[8] = {a0.x, a0.y, a0.z, a0.w, a1.x, a1.y, a1.z, a1.w};
            float bv[8] = {b0.x, b0.y, b0.z, b0.w, b1.x, b1.y, b1.z, b1.w};
#pragma unroll
            for (int i = 0; i < 8; ++i)
#pragma unroll
                for (int j = 0; j < 8; ++j)
                    acc[i][j] = fmaf(av[i], bv[j], acc[i][j]);
        }
    }

#pragma unroll
    for (int i = 0; i < 8; ++i) {
        float s2 = 0.f;
#pragma unroll
        for (int j = 0; j < 8; ++j) s2 = fmaf(acc[i][j], acc[i][j], s2);
        s2 += __shfl_xor_sync(0xffffffffu, s2, 1);
        s2 += __shfl_xor_sync(0xffffffffu, s2, 2);
        s2 += __shfl_xor_sync(0xffffffffu, s2, 4);
        float inv = 1.0f / sqrtf(s2);

        size_t off = (((size_t)(b * NSEL + warp) * LC) + (c0 + i)) * LT + l0;
        float4 v0 = make_float4(acc[i][0] * inv, acc[i][1] * inv,
                                acc[i][2] * inv, acc[i][3] * inv);
        float4 v1 = make_float4(acc[i][4] * inv, acc[i][5] * inv,
                                acc[i][6] * inv, acc[i][7] * inv);
        *(float4*)(out + off)     = v0;
        *(float4*)(out + off + 4) = v1;
    }
}

// ---------------------------------------------------------------------------
extern "C" void kernel_launch(void* const* d_in, const int* in_sizes, int n_in,
                              void* d_out, int out_size)
{
    const int*   claim   = nullptr;
    const int*   targets = nullptr;
    const float* emb     = nullptr;
    for (int i = 0; i < n_in; ++i) {
        if (in_sizes[i] == BATCH * LC)            claim   = (const int*)d_in[i];
        else if (in_sizes[i] == BATCH * TT * LT)  targets = (const int*)d_in[i];
        else if (in_sizes[i] == VOCAB * D)        emb     = (const float*)d_in[i];
        // n (size 1) is the compile-time constant NSEL=5; ignored.
    }
    float* out = (float*)d_out;

    cudaFuncSetAttribute(scores_kernel,
                         cudaFuncAttributeMaxDynamicSharedMemorySize, DYN_BYTES);

    scores_kernel<<<dim3(TT / 2, BATCH, 1), 128, DYN_BYTES>>>(claim, targets, emb);
    topk_kernel<<<BATCH, 32>>>();
    output_kernel<<<BATCH, 160>>>(claim, targets, emb, out);
}